// round 15
// baseline (speedup 1.0000x reference)
#include <cuda_runtime.h>
#include <cuda_bf16.h>
#include <cstdint>
#include <cstddef>
#include <cstring>

// Problem constants: B=4096, D=512, H=W=16 -> 2B = 8192 rows.
#define NB    4096
#define TWOB  8192
#define DDIM  512
#define GTILE 64                         // 8192 / 128 tiles per dim
#define NTRI  (GTILE * (GTILE + 1) / 2)  // 2080 upper-triangular tiles
#define LOG2E 1.4426950408889634f

// ---------------- device scratch (no allocs allowed) ----------------
__device__ __nv_bfloat16 g_X[(size_t)TWOB * DDIM];   // normalized [e1;e2], bf16
__device__ float g_inv_temp[TWOB];                   // invt * LOG2E (for ex2)
__device__ float g_pos[TWOB];                        // pos_sim / temp (natural)
__device__ float g_denom[TWOB];

__device__ __forceinline__ uint32_t pack_bf2(float a, float b) {
    __nv_bfloat162 h = __floats2bfloat162_rn(a, b);
    uint32_t u;
    memcpy(&u, &h, 4);
    return u;
}

__device__ __forceinline__ float ex2f(float x) {
    float y;
    asm("ex2.approx.ftz.f32 %0, %1;" : "=f"(y) : "f"(x));
    return y;
}

// ---------------- kernel 1: normalize + temp + pos + zero denom ------------
__global__ void __launch_bounds__(128) prep_kernel(const float* __restrict__ emb1,
                                                   const float* __restrict__ emb2,
                                                   const float* __restrict__ att) {
    const int row = blockIdx.x * 4 + (threadIdx.x >> 5);   // 0 .. NB-1
    const int lid = threadIdx.x & 31;

    const float4* p1 = (const float4*)(emb1 + (size_t)row * DDIM);
    const float4* p2 = (const float4*)(emb2 + (size_t)row * DDIM);
    const float4* pa = (const float4*)(att  + (size_t)row * 256);

    float4 v1[4], v2[4];
    #pragma unroll
    for (int i = 0; i < 4; ++i) v1[i] = p1[lid + 32 * i];
    #pragma unroll
    for (int i = 0; i < 4; ++i) v2[i] = p2[lid + 32 * i];
    float4 a0 = pa[lid], a1 = pa[lid + 32];

    float s1 = 0.0f, s2 = 0.0f, s12 = 0.0f;
    #pragma unroll
    for (int i = 0; i < 4; ++i) {
        s1  += v1[i].x * v1[i].x + v1[i].y * v1[i].y + v1[i].z * v1[i].z + v1[i].w * v1[i].w;
        s2  += v2[i].x * v2[i].x + v2[i].y * v2[i].y + v2[i].z * v2[i].z + v2[i].w * v2[i].w;
        s12 += v1[i].x * v2[i].x + v1[i].y * v2[i].y + v1[i].z * v2[i].z + v1[i].w * v2[i].w;
    }
    float a = a0.x + a0.y + a0.z + a0.w + a1.x + a1.y + a1.z + a1.w;

    #pragma unroll
    for (int o = 16; o; o >>= 1) {
        s1  += __shfl_xor_sync(0xFFFFFFFFu, s1,  o);
        s2  += __shfl_xor_sync(0xFFFFFFFFu, s2,  o);
        s12 += __shfl_xor_sync(0xFFFFFFFFu, s12, o);
        a   += __shfl_xor_sync(0xFFFFFFFFu, a,   o);
    }

    const float inv1 = 1.0f / fmaxf(sqrtf(s1), 1e-12f);
    const float inv2 = 1.0f / fmaxf(sqrtf(s2), 1e-12f);
    const float invt = 1.0f / (0.07f * (1.0f + 0.5f * (a * (1.0f / 256.0f))));
    const float pos  = s12 * inv1 * inv2 * invt;

    if (lid == 0) {
        const float it2 = invt * LOG2E;
        g_inv_temp[row]      = it2;
        g_inv_temp[row + NB] = it2;
        g_pos[row]      = pos;
        g_pos[row + NB] = pos;
        g_denom[row]      = 0.0f;
        g_denom[row + NB] = 0.0f;
    }

    uint2* x1 = (uint2*)(g_X + (size_t)row * DDIM);
    uint2* x2 = (uint2*)(g_X + (size_t)(row + NB) * DDIM);
    #pragma unroll
    for (int i = 0; i < 4; ++i) {
        uint2 w1, w2;
        w1.x = pack_bf2(v1[i].x * inv1, v1[i].y * inv1);
        w1.y = pack_bf2(v1[i].z * inv1, v1[i].w * inv1);
        w2.x = pack_bf2(v2[i].x * inv2, v2[i].y * inv2);
        w2.y = pack_bf2(v2[i].z * inv2, v2[i].w * inv2);
        x1[lid + 32 * i] = w1;
        x2[lid + 32 * i] = w2;
    }
}

// ---------------- kernel 2: fused Gram GEMM + exp row/col-sum (mma.sync) ----
// (R14 configuration — fully unrolled chunk loop, static stage addressing.
//  R15 delta: c+2 prefetch issued AFTER the ks=0 compute block so the first
//  fragment loads of each chunk aren't queued behind the LDGSTS burst.)
#define BK 64
#define TILE_B (128 * BK * 2)            // 16 KB per tile
#define STAGE_B (2 * TILE_B)             // A + B per stage = 32 KB
#define SMEM_BYTES (3 * STAGE_B)         // 96 KB

__device__ __forceinline__ uint32_t swz(int r, int c16) {
    return (uint32_t)(r * 128 + ((c16 ^ (r & 7)) << 4));
}

__device__ __forceinline__ void load_tile_async(uint32_t s_tile,
                                                const __nv_bfloat16* __restrict__ g,
                                                int t) {
    #pragma unroll
    for (int i = 0; i < 4; ++i) {
        int idx = t + i * 256;           // 1024 16B-chunks per tile
        int r = idx >> 3, c16 = idx & 7;
        uint32_t dst = s_tile + swz(r, c16);
        const void* src = g + (size_t)r * DDIM + c16 * 8;
        asm volatile("cp.async.cg.shared.global [%0], [%1], 16;"
                     :: "r"(dst), "l"(src) : "memory");
    }
}

__device__ __forceinline__ void ldsm_x4(uint32_t& r0, uint32_t& r1,
                                        uint32_t& r2, uint32_t& r3, uint32_t a) {
    asm volatile("ldmatrix.sync.aligned.m8n8.x4.shared.b16 {%0,%1,%2,%3}, [%4];"
                 : "=r"(r0), "=r"(r1), "=r"(r2), "=r"(r3) : "r"(a));
}

__device__ __forceinline__ void mma16816(float* c, uint32_t a0, uint32_t a1,
                                         uint32_t a2, uint32_t a3,
                                         uint32_t b0, uint32_t b1) {
    asm volatile(
        "mma.sync.aligned.m16n8k16.row.col.f32.bf16.bf16.f32 "
        "{%0,%1,%2,%3}, {%4,%5,%6,%7}, {%8,%9}, {%0,%1,%2,%3};"
        : "+f"(c[0]), "+f"(c[1]), "+f"(c[2]), "+f"(c[3])
        : "r"(a0), "r"(a1), "r"(a2), "r"(a3), "r"(b0), "r"(b1));
}

__global__ void __launch_bounds__(256, 2) gemm_kernel() {
    // --- triangular bid -> (by, bx), bx >= by ---
    const int bid = blockIdx.x;
    int by = (int)(0.5f * (129.0f - sqrtf(16641.0f - 8.0f * (float)bid)));
    while ((by + 1) * (129 - (by + 1)) / 2 <= bid) ++by;
    while (by * (129 - by) / 2 > bid) --by;
    const int bx = by + (bid - by * (129 - by) / 2);
    const bool diag = (bx == by);

    extern __shared__ char smem[];
    const uint32_t sbase = (uint32_t)__cvta_generic_to_shared(smem);

    const int t = threadIdx.x;
    const int wid = t >> 5, lid = t & 31;
    const int wr = wid >> 2;             // 0..1  (row group of 64)
    const int wc = wid & 3;              // 0..3  (col group of 32)
    const int row0 = by * 128;
    const int col0 = bx * 128;

    const __nv_bfloat16* Ag = g_X + (size_t)row0 * DDIM;
    const __nv_bfloat16* Bg = g_X + (size_t)col0 * DDIM;
    // diagonal tiles: B tile == A tile; alias smem and skip the B loads
    const uint32_t bOff = diag ? 0u : (uint32_t)TILE_B;

    float acc[4][4][4];
    #pragma unroll
    for (int mi = 0; mi < 4; ++mi)
        #pragma unroll
        for (int ni = 0; ni < 4; ++ni)
            #pragma unroll
            for (int k = 0; k < 4; ++k) acc[mi][ni][k] = 0.0f;

    const int a_r  = wr * 64 + (lid & 15);
    const int a_kg = (lid >> 4);
    const int b_r  = wc * 32 + (lid & 7) + ((lid >> 4) << 3);
    const int b_kg = (lid >> 3) & 1;

    // prologue: stages 0 and 1
    load_tile_async(sbase, Ag, t);
    if (!diag) load_tile_async(sbase + TILE_B, Bg, t);
    asm volatile("cp.async.commit_group;" ::: "memory");
    load_tile_async(sbase + STAGE_B, Ag + BK, t);
    if (!diag) load_tile_async(sbase + STAGE_B + TILE_B, Bg + BK, t);
    asm volatile("cp.async.commit_group;" ::: "memory");

    #pragma unroll
    for (int c = 0; c < 8; ++c) {
        if (c < 7) asm volatile("cp.async.wait_group 1;" ::: "memory");
        else       asm volatile("cp.async.wait_group 0;" ::: "memory");
        __syncthreads();

        const uint32_t sA = sbase + (c % 3) * STAGE_B;
        const uint32_t sB = sA + bOff;

        #pragma unroll
        for (int ks = 0; ks < 4; ++ks) {
            uint32_t b[8];
            #pragma unroll
            for (int nj = 0; nj < 2; ++nj) {
                int r = b_r + nj * 16;
                ldsm_x4(b[nj * 4 + 0], b[nj * 4 + 1], b[nj * 4 + 2], b[nj * 4 + 3],
                        sB + swz(r, ks * 2 + b_kg));
            }
            #pragma unroll
            for (int mi = 0; mi < 4; ++mi) {
                uint32_t a0, a1, a2, a3;
                ldsm_x4(a0, a1, a2, a3, sA + swz(a_r + mi * 16, ks * 2 + a_kg));
                #pragma unroll
                for (int ni = 0; ni < 4; ++ni) {
                    uint32_t* bp = &b[(ni >> 1) * 4 + (ni & 1) * 2];
                    mma16816(acc[mi][ni], a0, a1, a2, a3, bp[0], bp[1]);
                }
            }

            // issue chunk c+2 after the first compute batch of this chunk:
            // the LDGSTS burst now overlaps mma instead of preceding the
            // first fragment loads. Lead time stays ~1.75 chunks.
            if (ks == 0 && c + 2 < 8) {
                const uint32_t dA = sbase + ((c + 2) % 3) * STAGE_B;
                load_tile_async(dA, Ag + (c + 2) * BK, t);
                if (!diag) load_tile_async(dA + TILE_B, Bg + (c + 2) * BK, t);
                asm volatile("cp.async.commit_group;" ::: "memory");
            }
        }
    }

    // ---- epilogue (inv_temp pre-scaled by LOG2E; ex2 = 1 MUFU per term) ----
    const int groupID = lid >> 2;        // 0..7
    const int tig     = lid & 3;         // 0..3
    const int colBase = col0 + wc * 32;

    if (diag) {
        #pragma unroll
        for (int mi = 0; mi < 4; ++mi) {
            const int rA = row0 + wr * 64 + mi * 16 + groupID;
            const int rB = rA + 8;
            const float itA = g_inv_temp[rA];
            const float itB = g_inv_temp[rB];
            float sA_ = 0.0f, sB_ = 0.0f;
            #pragma unroll
            for (int ni = 0; ni < 4; ++ni) {
                const int c0 = colBase + ni * 8 + tig * 2;
                const int c1 = c0 + 1;
                if (c0 != rA) sA_ += ex2f(acc[mi][ni][0] * itA);
                if (c1 != rA) sA_ += ex2f(acc[mi][ni][1] * itA);
                if (c0 != rB) sB_ += ex2f(acc[mi][ni][2] * itB);
                if (c1 != rB) sB_ += ex2f(acc[mi][ni][3] * itB);
            }
            sA_ += __shfl_xor_sync(0xFFFFFFFFu, sA_, 1);
            sA_ += __shfl_xor_sync(0xFFFFFFFFu, sA_, 2);
            sB_ += __shfl_xor_sync(0xFFFFFFFFu, sB_, 1);
            sB_ += __shfl_xor_sync(0xFFFFFFFFu, sB_, 2);
            if (tig == 0) {
                atomicAdd(&g_denom[rA], sA_);
                atomicAdd(&g_denom[rB], sB_);
            }
        }
    } else {
        float it_c[4][2];
        #pragma unroll
        for (int ni = 0; ni < 4; ++ni) {
            it_c[ni][0] = g_inv_temp[colBase + ni * 8 + tig * 2];
            it_c[ni][1] = g_inv_temp[colBase + ni * 8 + tig * 2 + 1];
        }
        float csum[4][2];
        #pragma unroll
        for (int ni = 0; ni < 4; ++ni) { csum[ni][0] = 0.0f; csum[ni][1] = 0.0f; }

        #pragma unroll
        for (int mi = 0; mi < 4; ++mi) {
            const int rA = row0 + wr * 64 + mi * 16 + groupID;
            const int rB = rA + 8;
            const float itA = g_inv_temp[rA];
            const float itB = g_inv_temp[rB];
            float sA_ = 0.0f, sB_ = 0.0f;
            #pragma unroll
            for (int ni = 0; ni < 4; ++ni) {
                const float v0 = acc[mi][ni][0];
                const float v1 = acc[mi][ni][1];
                const float v2 = acc[mi][ni][2];
                const float v3 = acc[mi][ni][3];
                sA_ += ex2f(v0 * itA) + ex2f(v1 * itA);
                sB_ += ex2f(v2 * itB) + ex2f(v3 * itB);
                csum[ni][0] += ex2f(v0 * it_c[ni][0]) + ex2f(v2 * it_c[ni][0]);
                csum[ni][1] += ex2f(v1 * it_c[ni][1]) + ex2f(v3 * it_c[ni][1]);
            }
            sA_ += __shfl_xor_sync(0xFFFFFFFFu, sA_, 1);
            sA_ += __shfl_xor_sync(0xFFFFFFFFu, sA_, 2);
            sB_ += __shfl_xor_sync(0xFFFFFFFFu, sB_, 1);
            sB_ += __shfl_xor_sync(0xFFFFFFFFu, sB_, 2);
            if (tig == 0) {
                atomicAdd(&g_denom[rA], sA_);
                atomicAdd(&g_denom[rB], sB_);
            }
        }
        #pragma unroll
        for (int ni = 0; ni < 4; ++ni) {
            #pragma unroll
            for (int h = 0; h < 2; ++h) {
                float v = csum[ni][h];
                v += __shfl_xor_sync(0xFFFFFFFFu, v, 4);
                v += __shfl_xor_sync(0xFFFFFFFFu, v, 8);
                v += __shfl_xor_sync(0xFFFFFFFFu, v, 16);
                if (groupID == 0)
                    atomicAdd(&g_denom[colBase + ni * 8 + tig * 2 + h], v);
            }
        }
    }
}

// ---------------- kernel 3: loss = mean(log(denom) - pos) ----------------
__global__ void finalize_kernel(float* __restrict__ out, int out_size) {
    __shared__ float red[32];
    const int t = threadIdx.x;
    float s = 0.0f;
    #pragma unroll
    for (int i = 0; i < 8; ++i) {
        const int idx = t + i * 1024;
        s += __logf(g_denom[idx]) - g_pos[idx];
    }
    #pragma unroll
    for (int o = 16; o; o >>= 1) s += __shfl_xor_sync(0xFFFFFFFFu, s, o);
    if ((t & 31) == 0) red[t >> 5] = s;
    __syncthreads();
    if (t < 32) {
        float v = red[t];
        #pragma unroll
        for (int o = 16; o; o >>= 1) v += __shfl_xor_sync(0xFFFFFFFFu, v, o);
        if (t == 0) {
            float loss = v * (1.0f / (float)TWOB);
            for (int k = 0; k < out_size; ++k) out[k] = loss;
        }
    }
}

// ---------------- launch ----------------
extern "C" void kernel_launch(void* const* d_in, const int* in_sizes, int n_in,
                              void* d_out, int out_size) {
    const float* emb1 = (const float*)d_in[0];
    const float* emb2 = (const float*)d_in[1];
    const float* att  = (const float*)d_in[2];
    float* out = (float*)d_out;

    cudaFuncSetAttribute(gemm_kernel, cudaFuncAttributeMaxDynamicSharedMemorySize,
                         SMEM_BYTES);

    prep_kernel<<<NB / 4, 128>>>(emb1, emb2, att);   // rows 0..NB-1
    gemm_kernel<<<NTRI, 256, SMEM_BYTES>>>();
    finalize_kernel<<<1, 1024>>>(out, out_size);
}

// round 17
// speedup vs baseline: 1.0111x; 1.0111x over previous
#include <cuda_runtime.h>
#include <cuda_bf16.h>
#include <cstdint>
#include <cstddef>
#include <cstring>

// Problem constants: B=4096, D=512, H=W=16 -> 2B = 8192 rows.
#define NB    4096
#define TWOB  8192
#define DDIM  512
#define GTILE 64                         // 8192 / 128 tiles per dim
#define NTRI  (GTILE * (GTILE + 1) / 2)  // 2080 upper-triangular tiles
#define LOG2E 1.4426950408889634f

// ---------------- device scratch (no allocs allowed) ----------------
__device__ __nv_bfloat16 g_X[(size_t)TWOB * DDIM];   // normalized [e1;e2], bf16
__device__ float g_inv_temp[TWOB];                   // invt * LOG2E (for ex2)
__device__ float g_pos[TWOB];                        // pos_sim / temp (natural)
__device__ float g_denom[TWOB];

__device__ __forceinline__ uint32_t pack_bf2(float a, float b) {
    __nv_bfloat162 h = __floats2bfloat162_rn(a, b);
    uint32_t u;
    memcpy(&u, &h, 4);
    return u;
}

__device__ __forceinline__ float ex2f(float x) {
    float y;
    asm("ex2.approx.ftz.f32 %0, %1;" : "=f"(y) : "f"(x));
    return y;
}

// ---------------- kernel 1: normalize + temp + pos + zero denom ------------
__global__ void __launch_bounds__(128) prep_kernel(const float* __restrict__ emb1,
                                                   const float* __restrict__ emb2,
                                                   const float* __restrict__ att) {
    const int row = blockIdx.x * 4 + (threadIdx.x >> 5);   // 0 .. NB-1
    const int lid = threadIdx.x & 31;

    const float4* p1 = (const float4*)(emb1 + (size_t)row * DDIM);
    const float4* p2 = (const float4*)(emb2 + (size_t)row * DDIM);
    const float4* pa = (const float4*)(att  + (size_t)row * 256);

    float4 v1[4], v2[4];
    #pragma unroll
    for (int i = 0; i < 4; ++i) v1[i] = p1[lid + 32 * i];
    #pragma unroll
    for (int i = 0; i < 4; ++i) v2[i] = p2[lid + 32 * i];
    float4 a0 = pa[lid], a1 = pa[lid + 32];

    float s1 = 0.0f, s2 = 0.0f, s12 = 0.0f;
    #pragma unroll
    for (int i = 0; i < 4; ++i) {
        s1  += v1[i].x * v1[i].x + v1[i].y * v1[i].y + v1[i].z * v1[i].z + v1[i].w * v1[i].w;
        s2  += v2[i].x * v2[i].x + v2[i].y * v2[i].y + v2[i].z * v2[i].z + v2[i].w * v2[i].w;
        s12 += v1[i].x * v2[i].x + v1[i].y * v2[i].y + v1[i].z * v2[i].z + v1[i].w * v2[i].w;
    }
    float a = a0.x + a0.y + a0.z + a0.w + a1.x + a1.y + a1.z + a1.w;

    #pragma unroll
    for (int o = 16; o; o >>= 1) {
        s1  += __shfl_xor_sync(0xFFFFFFFFu, s1,  o);
        s2  += __shfl_xor_sync(0xFFFFFFFFu, s2,  o);
        s12 += __shfl_xor_sync(0xFFFFFFFFu, s12, o);
        a   += __shfl_xor_sync(0xFFFFFFFFu, a,   o);
    }

    const float inv1 = 1.0f / fmaxf(sqrtf(s1), 1e-12f);
    const float inv2 = 1.0f / fmaxf(sqrtf(s2), 1e-12f);
    const float invt = 1.0f / (0.07f * (1.0f + 0.5f * (a * (1.0f / 256.0f))));
    const float pos  = s12 * inv1 * inv2 * invt;

    if (lid == 0) {
        const float it2 = invt * LOG2E;
        g_inv_temp[row]      = it2;
        g_inv_temp[row + NB] = it2;
        g_pos[row]      = pos;
        g_pos[row + NB] = pos;
        g_denom[row]      = 0.0f;
        g_denom[row + NB] = 0.0f;
    }

    uint2* x1 = (uint2*)(g_X + (size_t)row * DDIM);
    uint2* x2 = (uint2*)(g_X + (size_t)(row + NB) * DDIM);
    #pragma unroll
    for (int i = 0; i < 4; ++i) {
        uint2 w1, w2;
        w1.x = pack_bf2(v1[i].x * inv1, v1[i].y * inv1);
        w1.y = pack_bf2(v1[i].z * inv1, v1[i].w * inv1);
        w2.x = pack_bf2(v2[i].x * inv2, v2[i].y * inv2);
        w2.y = pack_bf2(v2[i].z * inv2, v2[i].w * inv2);
        x1[lid + 32 * i] = w1;
        x2[lid + 32 * i] = w2;
    }
}

// ---------------- kernel 2: fused Gram GEMM + exp row/col-sum (mma.sync) ----
// (R14 configuration — best measured: triangular grid, 128x128 tiles,
//  3-stage BK=64 cp.async pipeline with fully-unrolled chunk loop (all smem
//  addressing compile-time constant), diag tiles alias B to A, ex2 epilogue.)
#define BK 64
#define TILE_B (128 * BK * 2)            // 16 KB per tile
#define STAGE_B (2 * TILE_B)             // A + B per stage = 32 KB
#define SMEM_BYTES (3 * STAGE_B)         // 96 KB

__device__ __forceinline__ uint32_t swz(int r, int c16) {
    return (uint32_t)(r * 128 + ((c16 ^ (r & 7)) << 4));
}

__device__ __forceinline__ void load_tile_async(uint32_t s_tile,
                                                const __nv_bfloat16* __restrict__ g,
                                                int t) {
    #pragma unroll
    for (int i = 0; i < 4; ++i) {
        int idx = t + i * 256;           // 1024 16B-chunks per tile
        int r = idx >> 3, c16 = idx & 7;
        uint32_t dst = s_tile + swz(r, c16);
        const void* src = g + (size_t)r * DDIM + c16 * 8;
        asm volatile("cp.async.cg.shared.global [%0], [%1], 16;"
                     :: "r"(dst), "l"(src) : "memory");
    }
}

__device__ __forceinline__ void ldsm_x4(uint32_t& r0, uint32_t& r1,
                                        uint32_t& r2, uint32_t& r3, uint32_t a) {
    asm volatile("ldmatrix.sync.aligned.m8n8.x4.shared.b16 {%0,%1,%2,%3}, [%4];"
                 : "=r"(r0), "=r"(r1), "=r"(r2), "=r"(r3) : "r"(a));
}

__device__ __forceinline__ void mma16816(float* c, uint32_t a0, uint32_t a1,
                                         uint32_t a2, uint32_t a3,
                                         uint32_t b0, uint32_t b1) {
    asm volatile(
        "mma.sync.aligned.m16n8k16.row.col.f32.bf16.bf16.f32 "
        "{%0,%1,%2,%3}, {%4,%5,%6,%7}, {%8,%9}, {%0,%1,%2,%3};"
        : "+f"(c[0]), "+f"(c[1]), "+f"(c[2]), "+f"(c[3])
        : "r"(a0), "r"(a1), "r"(a2), "r"(a3), "r"(b0), "r"(b1));
}

__global__ void __launch_bounds__(256, 2) gemm_kernel() {
    // --- triangular bid -> (by, bx), bx >= by ---
    const int bid = blockIdx.x;
    int by = (int)(0.5f * (129.0f - sqrtf(16641.0f - 8.0f * (float)bid)));
    while ((by + 1) * (129 - (by + 1)) / 2 <= bid) ++by;
    while (by * (129 - by) / 2 > bid) --by;
    const int bx = by + (bid - by * (129 - by) / 2);
    const bool diag = (bx == by);

    extern __shared__ char smem[];
    const uint32_t sbase = (uint32_t)__cvta_generic_to_shared(smem);

    const int t = threadIdx.x;
    const int wid = t >> 5, lid = t & 31;
    const int wr = wid >> 2;             // 0..1  (row group of 64)
    const int wc = wid & 3;              // 0..3  (col group of 32)
    const int row0 = by * 128;
    const int col0 = bx * 128;

    const __nv_bfloat16* Ag = g_X + (size_t)row0 * DDIM;
    const __nv_bfloat16* Bg = g_X + (size_t)col0 * DDIM;
    // diagonal tiles: B tile == A tile; alias smem and skip the B loads
    const uint32_t bOff = diag ? 0u : (uint32_t)TILE_B;

    float acc[4][4][4];
    #pragma unroll
    for (int mi = 0; mi < 4; ++mi)
        #pragma unroll
        for (int ni = 0; ni < 4; ++ni)
            #pragma unroll
            for (int k = 0; k < 4; ++k) acc[mi][ni][k] = 0.0f;

    const int a_r  = wr * 64 + (lid & 15);
    const int a_kg = (lid >> 4);
    const int b_r  = wc * 32 + (lid & 7) + ((lid >> 4) << 3);
    const int b_kg = (lid >> 3) & 1;

    // prologue: stages 0 and 1
    load_tile_async(sbase, Ag, t);
    if (!diag) load_tile_async(sbase + TILE_B, Bg, t);
    asm volatile("cp.async.commit_group;" ::: "memory");
    load_tile_async(sbase + STAGE_B, Ag + BK, t);
    if (!diag) load_tile_async(sbase + STAGE_B + TILE_B, Bg + BK, t);
    asm volatile("cp.async.commit_group;" ::: "memory");

    #pragma unroll
    for (int c = 0; c < 8; ++c) {
        if (c < 7) asm volatile("cp.async.wait_group 1;" ::: "memory");
        else       asm volatile("cp.async.wait_group 0;" ::: "memory");
        __syncthreads();

        // issue chunk c+2 into the freed stage first (static indices)
        if (c + 2 < 8) {
            const uint32_t dA = sbase + ((c + 2) % 3) * STAGE_B;
            load_tile_async(dA, Ag + (c + 2) * BK, t);
            if (!diag) load_tile_async(dA + TILE_B, Bg + (c + 2) * BK, t);
            asm volatile("cp.async.commit_group;" ::: "memory");
        }

        const uint32_t sA = sbase + (c % 3) * STAGE_B;
        const uint32_t sB = sA + bOff;

        #pragma unroll
        for (int ks = 0; ks < 4; ++ks) {
            uint32_t b[8];
            #pragma unroll
            for (int nj = 0; nj < 2; ++nj) {
                int r = b_r + nj * 16;
                ldsm_x4(b[nj * 4 + 0], b[nj * 4 + 1], b[nj * 4 + 2], b[nj * 4 + 3],
                        sB + swz(r, ks * 2 + b_kg));
            }
            #pragma unroll
            for (int mi = 0; mi < 4; ++mi) {
                uint32_t a0, a1, a2, a3;
                ldsm_x4(a0, a1, a2, a3, sA + swz(a_r + mi * 16, ks * 2 + a_kg));
                #pragma unroll
                for (int ni = 0; ni < 4; ++ni) {
                    uint32_t* bp = &b[(ni >> 1) * 4 + (ni & 1) * 2];
                    mma16816(acc[mi][ni], a0, a1, a2, a3, bp[0], bp[1]);
                }
            }
        }
    }

    // ---- epilogue (inv_temp pre-scaled by LOG2E; ex2 = 1 MUFU per term) ----
    const int groupID = lid >> 2;        // 0..7
    const int tig     = lid & 3;         // 0..3
    const int colBase = col0 + wc * 32;

    if (diag) {
        #pragma unroll
        for (int mi = 0; mi < 4; ++mi) {
            const int rA = row0 + wr * 64 + mi * 16 + groupID;
            const int rB = rA + 8;
            const float itA = g_inv_temp[rA];
            const float itB = g_inv_temp[rB];
            float sA_ = 0.0f, sB_ = 0.0f;
            #pragma unroll
            for (int ni = 0; ni < 4; ++ni) {
                const int c0 = colBase + ni * 8 + tig * 2;
                const int c1 = c0 + 1;
                if (c0 != rA) sA_ += ex2f(acc[mi][ni][0] * itA);
                if (c1 != rA) sA_ += ex2f(acc[mi][ni][1] * itA);
                if (c0 != rB) sB_ += ex2f(acc[mi][ni][2] * itB);
                if (c1 != rB) sB_ += ex2f(acc[mi][ni][3] * itB);
            }
            sA_ += __shfl_xor_sync(0xFFFFFFFFu, sA_, 1);
            sA_ += __shfl_xor_sync(0xFFFFFFFFu, sA_, 2);
            sB_ += __shfl_xor_sync(0xFFFFFFFFu, sB_, 1);
            sB_ += __shfl_xor_sync(0xFFFFFFFFu, sB_, 2);
            if (tig == 0) {
                atomicAdd(&g_denom[rA], sA_);
                atomicAdd(&g_denom[rB], sB_);
            }
        }
    } else {
        float it_c[4][2];
        #pragma unroll
        for (int ni = 0; ni < 4; ++ni) {
            it_c[ni][0] = g_inv_temp[colBase + ni * 8 + tig * 2];
            it_c[ni][1] = g_inv_temp[colBase + ni * 8 + tig * 2 + 1];
        }
        float csum[4][2];
        #pragma unroll
        for (int ni = 0; ni < 4; ++ni) { csum[ni][0] = 0.0f; csum[ni][1] = 0.0f; }

        #pragma unroll
        for (int mi = 0; mi < 4; ++mi) {
            const int rA = row0 + wr * 64 + mi * 16 + groupID;
            const int rB = rA + 8;
            const float itA = g_inv_temp[rA];
            const float itB = g_inv_temp[rB];
            float sA_ = 0.0f, sB_ = 0.0f;
            #pragma unroll
            for (int ni = 0; ni < 4; ++ni) {
                const float v0 = acc[mi][ni][0];
                const float v1 = acc[mi][ni][1];
                const float v2 = acc[mi][ni][2];
                const float v3 = acc[mi][ni][3];
                sA_ += ex2f(v0 * itA) + ex2f(v1 * itA);
                sB_ += ex2f(v2 * itB) + ex2f(v3 * itB);
                csum[ni][0] += ex2f(v0 * it_c[ni][0]) + ex2f(v2 * it_c[ni][0]);
                csum[ni][1] += ex2f(v1 * it_c[ni][1]) + ex2f(v3 * it_c[ni][1]);
            }
            sA_ += __shfl_xor_sync(0xFFFFFFFFu, sA_, 1);
            sA_ += __shfl_xor_sync(0xFFFFFFFFu, sA_, 2);
            sB_ += __shfl_xor_sync(0xFFFFFFFFu, sB_, 1);
            sB_ += __shfl_xor_sync(0xFFFFFFFFu, sB_, 2);
            if (tig == 0) {
                atomicAdd(&g_denom[rA], sA_);
                atomicAdd(&g_denom[rB], sB_);
            }
        }
        #pragma unroll
        for (int ni = 0; ni < 4; ++ni) {
            #pragma unroll
            for (int h = 0; h < 2; ++h) {
                float v = csum[ni][h];
                v += __shfl_xor_sync(0xFFFFFFFFu, v, 4);
                v += __shfl_xor_sync(0xFFFFFFFFu, v, 8);
                v += __shfl_xor_sync(0xFFFFFFFFu, v, 16);
                if (groupID == 0)
                    atomicAdd(&g_denom[colBase + ni * 8 + tig * 2 + h], v);
            }
        }
    }
}

// ---------------- kernel 3: loss = mean(log(denom) - pos) ----------------
__global__ void finalize_kernel(float* __restrict__ out, int out_size) {
    __shared__ float red[32];
    const int t = threadIdx.x;
    float s = 0.0f;
    #pragma unroll
    for (int i = 0; i < 8; ++i) {
        const int idx = t + i * 1024;
        s += __logf(g_denom[idx]) - g_pos[idx];
    }
    #pragma unroll
    for (int o = 16; o; o >>= 1) s += __shfl_xor_sync(0xFFFFFFFFu, s, o);
    if ((t & 31) == 0) red[t >> 5] = s;
    __syncthreads();
    if (t < 32) {
        float v = red[t];
        #pragma unroll
        for (int o = 16; o; o >>= 1) v += __shfl_xor_sync(0xFFFFFFFFu, v, o);
        if (t == 0) {
            float loss = v * (1.0f / (float)TWOB);
            for (int k = 0; k < out_size; ++k) out[k] = loss;
        }
    }
}

// ---------------- launch ----------------
extern "C" void kernel_launch(void* const* d_in, const int* in_sizes, int n_in,
                              void* d_out, int out_size) {
    const float* emb1 = (const float*)d_in[0];
    const float* emb2 = (const float*)d_in[1];
    const float* att  = (const float*)d_in[2];
    float* out = (float*)d_out;

    cudaFuncSetAttribute(gemm_kernel, cudaFuncAttributeMaxDynamicSharedMemorySize,
                         SMEM_BYTES);

    prep_kernel<<<NB / 4, 128>>>(emb1, emb2, att);   // rows 0..NB-1
    gemm_kernel<<<NTRI, 256, SMEM_BYTES>>>();
    finalize_kernel<<<1, 1024>>>(out, out_size);
}